// round 7
// baseline (speedup 1.0000x reference)
#include <cuda_runtime.h>
#include <math.h>

#define BB 16
#define TT 800
#define LL 160
#define DD 80
#define KK2 (2*DD)
#define HALF_LOG2PI 0.9189385332046727f
#define LOG2E_F 1.4426950408889634f
#define LN2_F   0.6931471805599453f
#define NEG_INF2 (-1.4426950408889634e20f)   // -1e20 in log2 units

__device__ __align__(16) float g_W[BB * KK2 * LL];   // [b][k][l]
__device__ __align__(16) float g_C[BB * LL];

// ---------------------------------------------------------------------------
// K0: per-(b,l) parameter transform. One warp per (b,l). Also zeroes the loss.
// ---------------------------------------------------------------------------
__global__ void param_kernel(const float* __restrict__ mu_sigma,
                             float* __restrict__ loss) {
    if (blockIdx.x == 0 && threadIdx.x == 0) *loss = 0.f;

    int wl   = (blockIdx.x * blockDim.x + threadIdx.x) >> 5;
    int lane = threadIdx.x & 31;
    if (wl >= BB * LL) return;
    int b = wl / LL, l = wl % LL;
    const float* ms = mu_sigma + (size_t)(b * LL + l) * KK2;

    float qmu = 0.f, sl = 0.f;
    for (int d = lane; d < DD; d += 32) {
        float mu = 4.f / (1.f + __expf(-ms[d]));
        float ls = 4.f * tanhf(ms[DD + d]);
        float iv = __expf(-2.f * ls);
        g_W[((size_t)b * KK2 + d)      * LL + l] = -0.5f * iv;
        g_W[((size_t)b * KK2 + DD + d) * LL + l] = mu * iv;
        qmu += mu * mu * iv;
        sl  += ls;
    }
#pragma unroll
    for (int o = 16; o; o >>= 1) {
        qmu += __shfl_xor_sync(0xffffffffu, qmu, o);
        sl  += __shfl_xor_sync(0xffffffffu, sl, o);
    }
    if (lane == 0)
        g_C[b * LL + l] = -0.5f * qmu - 0.5f * sl - (float)DD * HALF_LOG2PI;
}

// ---------------------------------------------------------------------------
// K1: lp[b,t,l] = sum_k X[t,k]*W[k,l] + C[l].  X = [mel^2 | mel] (K=160).
// 64x64 tile, BK=16, k-major smem (vector LDS for A and B), double-buffered,
// ONE __syncthreads per K-iter, LDG hoisted to iter top (latency hidden).
// ---------------------------------------------------------------------------
#define BK 16
__global__ void __launch_bounds__(256) lp_gemm(const float* __restrict__ mel,
                                               float* __restrict__ lp_out) {
    __shared__ __align__(16) float As[2][BK][68];   // [kk][mm], pad 68
    __shared__ __align__(16) float Bs[2][BK][64];   // [kk][nn]

    int b  = blockIdx.z;
    int m0 = blockIdx.x * 64;
    int n0 = blockIdx.y * 64;
    int tid = threadIdx.x;
    int tx = tid & 15, ty = tid >> 4;

    const float* melb = mel + (size_t)b * TT * DD;
    const float* Wb   = g_W + (size_t)b * KK2 * LL;

    // global-load mappings
    int a_mm = tid >> 2;            // 0..63 (t row within tile)
    int a_j4 = (tid & 3) * 4;       // k sub-offset 0,4,8,12
    int a_t  = m0 + a_mm; if (a_t > TT - 1) a_t = TT - 1;
    int b_kk = tid >> 4;            // 0..15 (k row)
    int b_l  = n0 + (tid & 15) * 4; // l col (mult of 4)
    bool b_ok = (b_l < LL);

    float acc[4][4];
#pragma unroll
    for (int i = 0; i < 4; i++)
#pragma unroll
        for (int j = 0; j < 4; j++) acc[i][j] = 0.f;

    // ---- prologue: load tile 0 into buffer 0
    float4 pa, pb;
    {
        const float* ap = melb + (size_t)a_t * DD + a_j4;   // k0=0 -> sq, kc=0
        pa = *(const float4*)ap;
        pa.x *= pa.x; pa.y *= pa.y; pa.z *= pa.z; pa.w *= pa.w;
        pb = b_ok ? *(const float4*)(Wb + (size_t)b_kk * LL + b_l)
                  : make_float4(0.f, 0.f, 0.f, 0.f);
        As[0][a_j4 + 0][a_mm] = pa.x;
        As[0][a_j4 + 1][a_mm] = pa.y;
        As[0][a_j4 + 2][a_mm] = pa.z;
        As[0][a_j4 + 3][a_mm] = pa.w;
        *(float4*)&Bs[0][b_kk][(tid & 15) * 4] = pb;
    }
    __syncthreads();

    for (int it = 0; it < KK2 / BK; it++) {
        int c = it & 1;
        // issue next tile's global loads early (latency hides under compute)
        if (it < KK2 / BK - 1) {
            int k0 = (it + 1) * BK;
            bool sq = (k0 < DD);
            int  kc = sq ? k0 : (k0 - DD);
            const float* ap = melb + (size_t)a_t * DD + kc + a_j4;
            pa = *(const float4*)ap;
            if (sq) { pa.x *= pa.x; pa.y *= pa.y; pa.z *= pa.z; pa.w *= pa.w; }
            pb = b_ok ? *(const float4*)(Wb + (size_t)(k0 + b_kk) * LL + b_l)
                      : make_float4(0.f, 0.f, 0.f, 0.f);
        }
        // compute on buffer c
#pragma unroll
        for (int kk = 0; kk < BK; kk++) {
            float4 av = *(const float4*)&As[c][kk][ty * 4];
            float4 bv = *(const float4*)&Bs[c][kk][tx * 4];
            acc[0][0] += av.x * bv.x; acc[0][1] += av.x * bv.y; acc[0][2] += av.x * bv.z; acc[0][3] += av.x * bv.w;
            acc[1][0] += av.y * bv.x; acc[1][1] += av.y * bv.y; acc[1][2] += av.y * bv.z; acc[1][3] += av.y * bv.w;
            acc[2][0] += av.z * bv.x; acc[2][1] += av.z * bv.y; acc[2][2] += av.z * bv.z; acc[2][3] += av.z * bv.w;
            acc[3][0] += av.w * bv.x; acc[3][1] += av.w * bv.y; acc[3][2] += av.w * bv.z; acc[3][3] += av.w * bv.w;
        }
        // stage next tile into the other buffer (written data ready post-compute)
        if (it < KK2 / BK - 1) {
            int n = c ^ 1;
            As[n][a_j4 + 0][a_mm] = pa.x;
            As[n][a_j4 + 1][a_mm] = pa.y;
            As[n][a_j4 + 2][a_mm] = pa.z;
            As[n][a_j4 + 3][a_mm] = pa.w;
            *(float4*)&Bs[n][b_kk][(tid & 15) * 4] = pb;
        }
        __syncthreads();
    }

    // epilogue: add C[l], guarded store
    float4 cv = make_float4(0.f, 0.f, 0.f, 0.f);
    if (n0 + tx * 4 < LL)
        cv = *(const float4*)(g_C + b * LL + n0 + tx * 4);
#pragma unroll
    for (int i = 0; i < 4; i++) {
        int t = m0 + ty * 4 + i;
        if (t >= TT) continue;
        if (n0 + tx * 4 < LL) {
            float4 o;
            o.x = acc[i][0] + cv.x; o.y = acc[i][1] + cv.y;
            o.z = acc[i][2] + cv.z; o.w = acc[i][3] + cv.w;
            *(float4*)(lp_out + ((size_t)b * TT + t) * LL + n0 + tx * 4) = o;
        }
    }
}

// ---------------------------------------------------------------------------
// K2: single-warp-per-batch scan, contiguous lane ownership l = 5*lane+k.
// Only chunk 0 needs a neighbor value (1 shfl/step); chunks 1-4 use the
// thread-local old alpha[k-1] (processed descending, in place). Log2 domain.
// ---------------------------------------------------------------------------
__device__ __forceinline__ float ex2f_(float x) {
    float r; asm("ex2.approx.ftz.f32 %0, %1;" : "=f"(r) : "f"(x)); return r;
}
__device__ __forceinline__ float lg2f_(float x) {
    float r; asm("lg2.approx.ftz.f32 %0, %1;" : "=f"(r) : "f"(x)); return r;
}
__device__ __forceinline__ float lse2_(float a, float p, float lpv) {
    float m = fmaxf(a, p);
    float d = fminf(a, p) - m;             // <= 0
    float s = lg2f_(1.f + ex2f_(d));
    return fmaf(lpv, LOG2E_F, m) + s;
}

__global__ void __launch_bounds__(32) scan_kernel(const float* __restrict__ lp,
                                                  float* __restrict__ alphas,
                                                  const int* __restrict__ ml,
                                                  const int* __restrict__ cl,
                                                  float* __restrict__ loss) {
    int b    = blockIdx.x;
    int lane = threadIdx.x;
    int lbase = lane * 5;

    const float* lpb = lp + (size_t)b * TT * LL;
    float* ab = alphas + (size_t)b * TT * LL;
    int mlb = ml[b] - 1;
    int clb = cl[b] - 1;
    int loss_lane = clb / 5, loss_k = clb % 5;

    float alpha[5];
#pragma unroll
    for (int k = 0; k < 5; k++) alpha[k] = NEG_INF2;
    if (lane == 0) alpha[0] = lpb[0] * LOG2E_F;

#pragma unroll
    for (int k = 0; k < 5; k++)
        ab[lbase + k] = alpha[k] * LN2_F;

    // depth-4 lp prefetch
    float pf[4][5];
#pragma unroll
    for (int r = 0; r < 4; r++)
#pragma unroll
        for (int k = 0; k < 5; k++)
            pf[r][k] = lpb[(size_t)(r + 1) * LL + lbase + k];

#pragma unroll 2
    for (int t = 1; t < TT; t++) {
        float lpv[5];
#pragma unroll
        for (int k = 0; k < 5; k++) {
            lpv[k] = pf[0][k];
            pf[0][k] = pf[1][k]; pf[1][k] = pf[2][k]; pf[2][k] = pf[3][k];
        }
        int tl = (t + 4 < TT) ? (t + 4) : (TT - 1);
        const float* pfrow = lpb + (size_t)tl * LL + lbase;
#pragma unroll
        for (int k = 0; k < 5; k++)
            pf[3][k] = pfrow[k];

        // neighbor: lane-1's old alpha[4]
        float top  = __shfl_up_sync(0xffffffffu, alpha[4], 1);
        float prev0 = lane ? top : NEG_INF2;

        // descending: alpha_new[k] from OLD alpha[k], alpha[k-1]
        alpha[4] = lse2_(alpha[4], alpha[3], lpv[4]);
        alpha[3] = lse2_(alpha[3], alpha[2], lpv[3]);
        alpha[2] = lse2_(alpha[2], alpha[1], lpv[2]);
        alpha[1] = lse2_(alpha[1], alpha[0], lpv[1]);
        alpha[0] = lse2_(alpha[0], prev0,   lpv[0]);

        float* row = ab + (size_t)t * LL + lbase;
        row[0] = alpha[0] * LN2_F;
        row[1] = alpha[1] * LN2_F;
        row[2] = alpha[2] * LN2_F;
        row[3] = alpha[3] * LN2_F;
        row[4] = alpha[4] * LN2_F;

        if (t == mlb && lane == loss_lane)
            atomicAdd(loss, -alpha[loss_k] * (LN2_F / (float)BB));
    }
}

// ---------------------------------------------------------------------------
extern "C" void kernel_launch(void* const* d_in, const int* in_sizes, int n_in,
                              void* d_out, int out_size) {
    const float* mel      = (const float*)d_in[0];
    const float* mu_sigma = (const float*)d_in[1];
    const int*   ml       = (const int*)d_in[2];
    const int*   cl       = (const int*)d_in[3];

    float* out    = (float*)d_out;
    float* lp     = out;                              // [B,T,L]
    float* loss   = out + (size_t)BB * TT * LL;       // [1]
    float* alphas = loss + 1;                         // [B,T,L]

    param_kernel<<<(BB * LL * 32 + 127) / 128, 128>>>(mu_sigma, loss);

    dim3 g((TT + 63) / 64, (LL + 63) / 64, BB);       // 13 x 3 x 16
    lp_gemm<<<g, 256>>>(mel, lp);

    scan_kernel<<<BB, 32>>>(lp, alphas, ml, cl, loss);
}

// round 8
// speedup vs baseline: 1.2502x; 1.2502x over previous
#include <cuda_runtime.h>
#include <math.h>

#define BB 16
#define TT 800
#define LL 160
#define DD 80
#define KK2 (2*DD)
#define HALF_LOG2PI 0.9189385332046727f
#define LOG2E_F 1.4426950408889634f
#define LN2_F   0.6931471805599453f
#define NEG_INF2 (-1.4426950408889634e20f)   // -1e20 in log2 units

__device__ __align__(16) float g_W[BB * KK2 * LL];   // [b][k][l]
__device__ __align__(16) float g_C[BB * LL];

// ---------------------------------------------------------------------------
// K0: per-(b,l) parameter transform. One warp per (b,l). Also zeroes the loss.
// ---------------------------------------------------------------------------
__global__ void param_kernel(const float* __restrict__ mu_sigma,
                             float* __restrict__ loss) {
    if (blockIdx.x == 0 && threadIdx.x == 0) *loss = 0.f;

    int wl   = (blockIdx.x * blockDim.x + threadIdx.x) >> 5;
    int lane = threadIdx.x & 31;
    if (wl >= BB * LL) return;
    int b = wl / LL, l = wl % LL;
    const float* ms = mu_sigma + (size_t)(b * LL + l) * KK2;

    float qmu = 0.f, sl = 0.f;
    for (int d = lane; d < DD; d += 32) {
        float mu = 4.f / (1.f + __expf(-ms[d]));
        float ls = 4.f * tanhf(ms[DD + d]);
        float iv = __expf(-2.f * ls);
        g_W[((size_t)b * KK2 + d)      * LL + l] = -0.5f * iv;
        g_W[((size_t)b * KK2 + DD + d) * LL + l] = mu * iv;
        qmu += mu * mu * iv;
        sl  += ls;
    }
#pragma unroll
    for (int o = 16; o; o >>= 1) {
        qmu += __shfl_xor_sync(0xffffffffu, qmu, o);
        sl  += __shfl_xor_sync(0xffffffffu, sl, o);
    }
    if (lane == 0)
        g_C[b * LL + l] = -0.5f * qmu - 0.5f * sl - (float)DD * HALF_LOG2PI;
}

// ---------------------------------------------------------------------------
// K1: the ROUND-1 GEMM, reverted verbatim (known 176-us-build component) so
// this round's delta is attributable purely to the scan change.
// ---------------------------------------------------------------------------
#define BK 16
__global__ void __launch_bounds__(256) lp_gemm(const float* __restrict__ mel,
                                               float* __restrict__ lp_out) {
    __shared__ float As[64][BK + 1];
    __shared__ float Bs[BK][64];

    int b  = blockIdx.z;
    int m0 = blockIdx.x * 64;
    int n0 = blockIdx.y * 64;
    int tid = threadIdx.x;
    int tx = tid & 15, ty = tid >> 4;

    const float* melb = mel + (size_t)b * TT * DD;
    const float* Wb   = g_W + (size_t)b * KK2 * LL;

    float acc[4][4];
#pragma unroll
    for (int i = 0; i < 4; i++)
#pragma unroll
        for (int j = 0; j < 4; j++) acc[i][j] = 0.f;

    for (int k0 = 0; k0 < KK2; k0 += BK) {
        bool sq = (k0 < DD);
        int  kc = sq ? k0 : (k0 - DD);
#pragma unroll
        for (int i = 0; i < 4; i++) {
            int lin = tid + i * 256;
            int mm = lin >> 4, kk = lin & 15;
            int t = m0 + mm; if (t > TT - 1) t = TT - 1;
            float v = melb[(size_t)t * DD + kc + kk];
            As[mm][kk] = sq ? v * v : v;
        }
#pragma unroll
        for (int i = 0; i < 4; i++) {
            int lin = tid + i * 256;
            int kk = lin >> 6, nn = lin & 63;
            int l = n0 + nn;
            Bs[kk][nn] = (l < LL) ? Wb[(size_t)(k0 + kk) * LL + l] : 0.f;
        }
        __syncthreads();
#pragma unroll
        for (int kk = 0; kk < BK; kk++) {
            float a0 = As[ty * 4 + 0][kk];
            float a1 = As[ty * 4 + 1][kk];
            float a2 = As[ty * 4 + 2][kk];
            float a3 = As[ty * 4 + 3][kk];
            float4 bv = *(const float4*)&Bs[kk][tx * 4];
            acc[0][0] += a0 * bv.x; acc[0][1] += a0 * bv.y; acc[0][2] += a0 * bv.z; acc[0][3] += a0 * bv.w;
            acc[1][0] += a1 * bv.x; acc[1][1] += a1 * bv.y; acc[1][2] += a1 * bv.z; acc[1][3] += a1 * bv.w;
            acc[2][0] += a2 * bv.x; acc[2][1] += a2 * bv.y; acc[2][2] += a2 * bv.z; acc[2][3] += a2 * bv.w;
            acc[3][0] += a3 * bv.x; acc[3][1] += a3 * bv.y; acc[3][2] += a3 * bv.z; acc[3][3] += a3 * bv.w;
        }
        __syncthreads();
    }

#pragma unroll
    for (int i = 0; i < 4; i++) {
        int t = m0 + ty * 4 + i;
        if (t >= TT) continue;
#pragma unroll
        for (int j = 0; j < 4; j++) {
            int l = n0 + tx * 4 + j;
            if (l < LL)
                lp_out[((size_t)b * TT + t) * LL + l] = acc[i][j] + g_C[b * LL + l];
        }
    }
}

// ---------------------------------------------------------------------------
// K2: SLIM single-warp scan. Contiguous ownership l = 5*lane+k (1 shfl/step).
// Issue-minimized: pointer-bump addressing with immediate offsets (no per-step
// IMADs), unroll-4 with statically-indexed prefetch slots (no MOV shifting).
// Log2 domain; outputs converted by *LN2 at store. Loss fused (predicated).
// ---------------------------------------------------------------------------
__device__ __forceinline__ float ex2f_(float x) {
    float r; asm("ex2.approx.ftz.f32 %0, %1;" : "=f"(r) : "f"(x)); return r;
}
__device__ __forceinline__ float lg2f_(float x) {
    float r; asm("lg2.approx.ftz.f32 %0, %1;" : "=f"(r) : "f"(x)); return r;
}
__device__ __forceinline__ float lse2_(float a, float p, float lpv) {
    float m = fmaxf(a, p);
    float d = fminf(a, p) - m;             // <= 0
    float s = lg2f_(1.f + ex2f_(d));
    return fmaf(lpv, LOG2E_F, m) + s;
}

__global__ void __launch_bounds__(32) scan_kernel(const float* __restrict__ lp,
                                                  float* __restrict__ alphas,
                                                  const int* __restrict__ ml,
                                                  const int* __restrict__ cl,
                                                  float* __restrict__ loss) {
    int b    = blockIdx.x;
    int lane = threadIdx.x;
    int lbase = lane * 5;

    const float* lpb = lp + (size_t)b * TT * LL;
    float* ab = alphas + (size_t)b * TT * LL;
    int mlb = ml[b] - 1;
    int clb = cl[b] - 1;
    int loss_lane = clb / 5, loss_k = clb % 5;
    bool is_loss_lane = (lane == loss_lane);

    float alpha[5];
#pragma unroll
    for (int k = 0; k < 5; k++) alpha[k] = NEG_INF2;
    if (lane == 0) alpha[0] = lpb[0] * LOG2E_F;

#pragma unroll
    for (int k = 0; k < 5; k++)
        ab[lbase + k] = alpha[k] * LN2_F;

    // prefetch rows 1..4 into statically-indexed slots; pfp then points to row 5
    float pf[4][5];
    const float* pfp = lpb + LL + lbase;
#pragma unroll
    for (int r = 0; r < 4; r++) {
#pragma unroll
        for (int k = 0; k < 5; k++) pf[r][k] = pfp[k];
        pfp += LL;
    }
    float* abp = ab + LL + lbase;    // store pointer for t = 1

    int t = 1;
    // 199 groups of 4 -> t = 1..796. Group body: slot u consumed, then
    // reloaded with row t+4 (consumed again 4 steps later; distance ~340 cyc).
    // NOTE: at t=796 the reload reads "row 800" (next batch / loss area) --
    // within the d_out allocation and never consumed: the epilogue only uses
    // slots 0..2.
    for (int g = 0; g < 199; g++) {
#pragma unroll
        for (int u = 0; u < 4; u++) {
            float top   = __shfl_up_sync(0xffffffffu, alpha[4], 1);
            float prev0 = lane ? top : NEG_INF2;

            alpha[4] = lse2_(alpha[4], alpha[3], pf[u][4]);
            alpha[3] = lse2_(alpha[3], alpha[2], pf[u][3]);
            alpha[2] = lse2_(alpha[2], alpha[1], pf[u][2]);
            alpha[1] = lse2_(alpha[1], alpha[0], pf[u][1]);
            alpha[0] = lse2_(alpha[0], prev0,   pf[u][0]);

            // reload this slot with row t+4 (immediate offsets off pfp)
#pragma unroll
            for (int k = 0; k < 5; k++) pf[u][k] = pfp[k];
            pfp += LL;

            // stores (immediate offsets off abp)
            abp[0] = alpha[0] * LN2_F;
            abp[1] = alpha[1] * LN2_F;
            abp[2] = alpha[2] * LN2_F;
            abp[3] = alpha[3] * LN2_F;
            abp[4] = alpha[4] * LN2_F;
            abp += LL;

            if (t == mlb && is_loss_lane)
                atomicAdd(loss, -alpha[loss_k] * (LN2_F / (float)BB));
            t++;
        }
    }
    // epilogue: t = 797, 798, 799 from slots 0..2 (rows 797..799)
#pragma unroll
    for (int u = 0; u < 3; u++) {
        float top   = __shfl_up_sync(0xffffffffu, alpha[4], 1);
        float prev0 = lane ? top : NEG_INF2;

        alpha[4] = lse2_(alpha[4], alpha[3], pf[u][4]);
        alpha[3] = lse2_(alpha[3], alpha[2], pf[u][3]);
        alpha[2] = lse2_(alpha[2], alpha[1], pf[u][2]);
        alpha[1] = lse2_(alpha[1], alpha[0], pf[u][1]);
        alpha[0] = lse2_(alpha[0], prev0,   pf[u][0]);

        abp[0] = alpha[0] * LN2_F;
        abp[1] = alpha[1] * LN2_F;
        abp[2] = alpha[2] * LN2_F;
        abp[3] = alpha[3] * LN2_F;
        abp[4] = alpha[4] * LN2_F;
        abp += LL;

        if (t == mlb && is_loss_lane)
            atomicAdd(loss, -alpha[loss_k] * (LN2_F / (float)BB));
        t++;
    }
}

// ---------------------------------------------------------------------------
extern "C" void kernel_launch(void* const* d_in, const int* in_sizes, int n_in,
                              void* d_out, int out_size) {
    const float* mel      = (const float*)d_in[0];
    const float* mu_sigma = (const float*)d_in[1];
    const int*   ml       = (const int*)d_in[2];
    const int*   cl       = (const int*)d_in[3];

    float* out    = (float*)d_out;
    float* lp     = out;                              // [B,T,L]
    float* loss   = out + (size_t)BB * TT * LL;       // [1]
    float* alphas = loss + 1;                         // [B,T,L]

    param_kernel<<<(BB * LL * 32 + 127) / 128, 128>>>(mu_sigma, loss);

    dim3 g((TT + 63) / 64, (LL + 63) / 64, BB);       // 13 x 3 x 16
    lp_gemm<<<g, 256>>>(mel, lp);

    scan_kernel<<<BB, 32>>>(lp, alphas, ml, cl, loss);
}

// round 9
// speedup vs baseline: 1.2837x; 1.0268x over previous
#include <cuda_runtime.h>
#include <math.h>

#define BB 16
#define TT 800
#define LL 160
#define DD 80
#define KK2 (2*DD)
#define HALF_LOG2PI 0.9189385332046727f
#define LOG2E_F 1.4426950408889634f
#define LN2_F   0.6931471805599453f
#define NEG_INF2 (-1.4426950408889634e20f)   // -1e20 in log2 units

__device__ __align__(16) float g_W[BB * KK2 * LL];   // [b][k][l]
__device__ __align__(16) float g_C[BB * LL];

// ---------------------------------------------------------------------------
// K0: per-(b,l) parameter transform. One warp per (b,l). Also zeroes the loss.
// (unchanged from R8)
// ---------------------------------------------------------------------------
__global__ void param_kernel(const float* __restrict__ mu_sigma,
                             float* __restrict__ loss) {
    if (blockIdx.x == 0 && threadIdx.x == 0) *loss = 0.f;

    int wl   = (blockIdx.x * blockDim.x + threadIdx.x) >> 5;
    int lane = threadIdx.x & 31;
    if (wl >= BB * LL) return;
    int b = wl / LL, l = wl % LL;
    const float* ms = mu_sigma + (size_t)(b * LL + l) * KK2;

    float qmu = 0.f, sl = 0.f;
    for (int d = lane; d < DD; d += 32) {
        float mu = 4.f / (1.f + __expf(-ms[d]));
        float ls = 4.f * tanhf(ms[DD + d]);
        float iv = __expf(-2.f * ls);
        g_W[((size_t)b * KK2 + d)      * LL + l] = -0.5f * iv;
        g_W[((size_t)b * KK2 + DD + d) * LL + l] = mu * iv;
        qmu += mu * mu * iv;
        sl  += ls;
    }
#pragma unroll
    for (int o = 16; o; o >>= 1) {
        qmu += __shfl_xor_sync(0xffffffffu, qmu, o);
        sl  += __shfl_xor_sync(0xffffffffu, sl, o);
    }
    if (lane == 0)
        g_C[b * LL + l] = -0.5f * qmu - 0.5f * sl - (float)DD * HALF_LOG2PI;
}

// ---------------------------------------------------------------------------
// K1: NEW GEMM. lp[b,t,l] = sum_d mel2[t,d]*W1[d,l] + mel[t,d]*W2[d,l] + C[l].
// A tile = RAW mel (loaded once over D=80 -> 5 iters of BK=16), squared in
// registers at use. Two B tiles per iter (W rows d and 80+d). Register
// prefetch of next iter's tiles hides LDG latency; 2 barriers/iter x 5 iters
// (vs 20 barriers + exposed LDG before). Smem layouts = proven R1 patterns.
// ---------------------------------------------------------------------------
#define BK 16
__global__ void __launch_bounds__(256) lp_gemm(const float* __restrict__ mel,
                                               float* __restrict__ lp_out) {
    __shared__ float As [64][BK + 1];   // raw mel, [mm][kk]
    __shared__ float Bs1[BK][64];       // -0.5*inv_var rows
    __shared__ float Bs2[BK][64];       // mu*inv_var rows

    int b  = blockIdx.z;
    int m0 = blockIdx.x * 64;
    int n0 = blockIdx.y * 64;
    int tid = threadIdx.x;
    int tx = tid & 15, ty = tid >> 4;

    const float* melb = mel + (size_t)b * TT * DD;
    const float* Wb   = g_W + (size_t)b * KK2 * LL;

    // load-mapping constants (A: 4 scalars/thread; B1/B2: 4 scalars/thread)
    int a_mm[4], a_kk[4], bl_kk[4], bl_nn[4];
    bool bl_ok[4];
    int a_t[4];
#pragma unroll
    for (int i = 0; i < 4; i++) {
        int lin = tid + i * 256;
        a_mm[i] = lin >> 4;  a_kk[i] = lin & 15;
        int t = m0 + a_mm[i]; if (t > TT - 1) t = TT - 1;
        a_t[i] = t;
        bl_kk[i] = lin >> 6; bl_nn[i] = lin & 63;
        bl_ok[i] = (n0 + bl_nn[i]) < LL;
    }

    float acc[4][4];
#pragma unroll
    for (int i = 0; i < 4; i++)
#pragma unroll
        for (int j = 0; j < 4; j++) acc[i][j] = 0.f;

    // ---- prologue: iter 0 tiles straight to smem
#pragma unroll
    for (int i = 0; i < 4; i++) {
        As[a_mm[i]][a_kk[i]] = melb[(size_t)a_t[i] * DD + a_kk[i]];
        int l = n0 + bl_nn[i];
        Bs1[bl_kk[i]][bl_nn[i]] = bl_ok[i] ? Wb[(size_t)bl_kk[i] * LL + l] : 0.f;
        Bs2[bl_kk[i]][bl_nn[i]] = bl_ok[i] ? Wb[(size_t)(DD + bl_kk[i]) * LL + l] : 0.f;
    }
    __syncthreads();

    float ra[4], rb1[4], rb2[4];
    for (int it = 0; it < DD / BK; it++) {
        // prefetch next iter's tiles into registers (latency under compute)
        if (it < DD / BK - 1) {
            int k0 = (it + 1) * BK;
#pragma unroll
            for (int i = 0; i < 4; i++) {
                ra[i] = melb[(size_t)a_t[i] * DD + k0 + a_kk[i]];
                int l = n0 + bl_nn[i];
                rb1[i] = bl_ok[i] ? Wb[(size_t)(k0 + bl_kk[i]) * LL + l] : 0.f;
                rb2[i] = bl_ok[i] ? Wb[(size_t)(DD + k0 + bl_kk[i]) * LL + l] : 0.f;
            }
        }
        // compute: both K-halves from one raw A tile
#pragma unroll
        for (int kk = 0; kk < BK; kk++) {
            float a0 = As[ty * 4 + 0][kk];
            float a1 = As[ty * 4 + 1][kk];
            float a2 = As[ty * 4 + 2][kk];
            float a3 = As[ty * 4 + 3][kk];
            float q0 = a0 * a0, q1 = a1 * a1, q2 = a2 * a2, q3 = a3 * a3;
            float4 b1 = *(const float4*)&Bs1[kk][tx * 4];
            float4 b2 = *(const float4*)&Bs2[kk][tx * 4];
            acc[0][0] += q0 * b1.x; acc[0][1] += q0 * b1.y; acc[0][2] += q0 * b1.z; acc[0][3] += q0 * b1.w;
            acc[1][0] += q1 * b1.x; acc[1][1] += q1 * b1.y; acc[1][2] += q1 * b1.z; acc[1][3] += q1 * b1.w;
            acc[2][0] += q2 * b1.x; acc[2][1] += q2 * b1.y; acc[2][2] += q2 * b1.z; acc[2][3] += q2 * b1.w;
            acc[3][0] += q3 * b1.x; acc[3][1] += q3 * b1.y; acc[3][2] += q3 * b1.z; acc[3][3] += q3 * b1.w;
            acc[0][0] += a0 * b2.x; acc[0][1] += a0 * b2.y; acc[0][2] += a0 * b2.z; acc[0][3] += a0 * b2.w;
            acc[1][0] += a1 * b2.x; acc[1][1] += a1 * b2.y; acc[1][2] += a1 * b2.z; acc[1][3] += a1 * b2.w;
            acc[2][0] += a2 * b2.x; acc[2][1] += a2 * b2.y; acc[2][2] += a2 * b2.z; acc[2][3] += a2 * b2.w;
            acc[3][0] += a3 * b2.x; acc[3][1] += a3 * b2.y; acc[3][2] += a3 * b2.z; acc[3][3] += a3 * b2.w;
        }
        __syncthreads();                    // everyone done reading smem
        if (it < DD / BK - 1) {
#pragma unroll
            for (int i = 0; i < 4; i++) {
                As[a_mm[i]][a_kk[i]]    = ra[i];
                Bs1[bl_kk[i]][bl_nn[i]] = rb1[i];
                Bs2[bl_kk[i]][bl_nn[i]] = rb2[i];
            }
            __syncthreads();                // staged tiles visible
        }
    }

    // epilogue: + C[l], guarded scalar stores (R1-proven)
#pragma unroll
    for (int i = 0; i < 4; i++) {
        int t = m0 + ty * 4 + i;
        if (t >= TT) continue;
#pragma unroll
        for (int j = 0; j < 4; j++) {
            int l = n0 + tx * 4 + j;
            if (l < LL)
                lp_out[((size_t)b * TT + t) * LL + l] = acc[i][j] + g_C[b * LL + l];
        }
    }
}

// ---------------------------------------------------------------------------
// K2: SLIM single-warp scan (byte-identical to R8 best).
// ---------------------------------------------------------------------------
__device__ __forceinline__ float ex2f_(float x) {
    float r; asm("ex2.approx.ftz.f32 %0, %1;" : "=f"(r) : "f"(x)); return r;
}
__device__ __forceinline__ float lg2f_(float x) {
    float r; asm("lg2.approx.ftz.f32 %0, %1;" : "=f"(r) : "f"(x)); return r;
}
__device__ __forceinline__ float lse2_(float a, float p, float lpv) {
    float m = fmaxf(a, p);
    float d = fminf(a, p) - m;             // <= 0
    float s = lg2f_(1.f + ex2f_(d));
    return fmaf(lpv, LOG2E_F, m) + s;
}

__global__ void __launch_bounds__(32) scan_kernel(const float* __restrict__ lp,
                                                  float* __restrict__ alphas,
                                                  const int* __restrict__ ml,
                                                  const int* __restrict__ cl,
                                                  float* __restrict__ loss) {
    int b    = blockIdx.x;
    int lane = threadIdx.x;
    int lbase = lane * 5;

    const float* lpb = lp + (size_t)b * TT * LL;
    float* ab = alphas + (size_t)b * TT * LL;
    int mlb = ml[b] - 1;
    int clb = cl[b] - 1;
    int loss_lane = clb / 5, loss_k = clb % 5;
    bool is_loss_lane = (lane == loss_lane);

    float alpha[5];
#pragma unroll
    for (int k = 0; k < 5; k++) alpha[k] = NEG_INF2;
    if (lane == 0) alpha[0] = lpb[0] * LOG2E_F;

#pragma unroll
    for (int k = 0; k < 5; k++)
        ab[lbase + k] = alpha[k] * LN2_F;

    float pf[4][5];
    const float* pfp = lpb + LL + lbase;
#pragma unroll
    for (int r = 0; r < 4; r++) {
#pragma unroll
        for (int k = 0; k < 5; k++) pf[r][k] = pfp[k];
        pfp += LL;
    }
    float* abp = ab + LL + lbase;

    int t = 1;
    for (int g = 0; g < 199; g++) {
#pragma unroll
        for (int u = 0; u < 4; u++) {
            float top   = __shfl_up_sync(0xffffffffu, alpha[4], 1);
            float prev0 = lane ? top : NEG_INF2;

            alpha[4] = lse2_(alpha[4], alpha[3], pf[u][4]);
            alpha[3] = lse2_(alpha[3], alpha[2], pf[u][3]);
            alpha[2] = lse2_(alpha[2], alpha[1], pf[u][2]);
            alpha[1] = lse2_(alpha[1], alpha[0], pf[u][1]);
            alpha[0] = lse2_(alpha[0], prev0,   pf[u][0]);

#pragma unroll
            for (int k = 0; k < 5; k++) pf[u][k] = pfp[k];
            pfp += LL;

            abp[0] = alpha[0] * LN2_F;
            abp[1] = alpha[1] * LN2_F;
            abp[2] = alpha[2] * LN2_F;
            abp[3] = alpha[3] * LN2_F;
            abp[4] = alpha[4] * LN2_F;
            abp += LL;

            if (t == mlb && is_loss_lane)
                atomicAdd(loss, -alpha[loss_k] * (LN2_F / (float)BB));
            t++;
        }
    }
#pragma unroll
    for (int u = 0; u < 3; u++) {
        float top   = __shfl_up_sync(0xffffffffu, alpha[4], 1);
        float prev0 = lane ? top : NEG_INF2;

        alpha[4] = lse2_(alpha[4], alpha[3], pf[u][4]);
        alpha[3] = lse2_(alpha[3], alpha[2], pf[u][3]);
        alpha[2] = lse2_(alpha[2], alpha[1], pf[u][2]);
        alpha[1] = lse2_(alpha[1], alpha[0], pf[u][1]);
        alpha[0] = lse2_(alpha[0], prev0,   pf[u][0]);

        abp[0] = alpha[0] * LN2_F;
        abp[1] = alpha[1] * LN2_F;
        abp[2] = alpha[2] * LN2_F;
        abp[3] = alpha[3] * LN2_F;
        abp[4] = alpha[4] * LN2_F;
        abp += LL;

        if (t == mlb && is_loss_lane)
            atomicAdd(loss, -alpha[loss_k] * (LN2_F / (float)BB));
        t++;
    }
}

// ---------------------------------------------------------------------------
extern "C" void kernel_launch(void* const* d_in, const int* in_sizes, int n_in,
                              void* d_out, int out_size) {
    const float* mel      = (const float*)d_in[0];
    const float* mu_sigma = (const float*)d_in[1];
    const int*   ml       = (const int*)d_in[2];
    const int*   cl       = (const int*)d_in[3];

    float* out    = (float*)d_out;
    float* lp     = out;                              // [B,T,L]
    float* loss   = out + (size_t)BB * TT * LL;       // [1]
    float* alphas = loss + 1;                         // [B,T,L]

    param_kernel<<<(BB * LL * 32 + 127) / 128, 128>>>(mu_sigma, loss);

    dim3 g((TT + 63) / 64, (LL + 63) / 64, BB);       // 13 x 3 x 16
    lp_gemm<<<g, 256>>>(mel, lp);

    scan_kernel<<<BB, 32>>>(lp, alphas, ml, cl, loss);
}

// round 10
// speedup vs baseline: 1.6637x; 1.2960x over previous
#include <cuda_runtime.h>
#include <math.h>

#define BB 16
#define TT 800
#define LL 160
#define DD 80
#define KK2 (2*DD)
#define HALF_LOG2PI 0.9189385332046727f
#define LOG2E_F 1.4426950408889634f
#define LN2_F   0.6931471805599453f
#define NEG_INF2 (-1.4426950408889634e20f)   // -1e20 in log2 units

__device__ __align__(16) float g_W[BB * KK2 * LL];   // [b][k][l]
__device__ __align__(16) float g_C[BB * LL];

// ---------------------------------------------------------------------------
// K0: per-(b,l) parameter transform (unchanged from R9).
// ---------------------------------------------------------------------------
__global__ void param_kernel(const float* __restrict__ mu_sigma,
                             float* __restrict__ loss) {
    if (blockIdx.x == 0 && threadIdx.x == 0) *loss = 0.f;

    int wl   = (blockIdx.x * blockDim.x + threadIdx.x) >> 5;
    int lane = threadIdx.x & 31;
    if (wl >= BB * LL) return;
    int b = wl / LL, l = wl % LL;
    const float* ms = mu_sigma + (size_t)(b * LL + l) * KK2;

    float qmu = 0.f, sl = 0.f;
    for (int d = lane; d < DD; d += 32) {
        float mu = 4.f / (1.f + __expf(-ms[d]));
        float ls = 4.f * tanhf(ms[DD + d]);
        float iv = __expf(-2.f * ls);
        g_W[((size_t)b * KK2 + d)      * LL + l] = -0.5f * iv;
        g_W[((size_t)b * KK2 + DD + d) * LL + l] = mu * iv;
        qmu += mu * mu * iv;
        sl  += ls;
    }
#pragma unroll
    for (int o = 16; o; o >>= 1) {
        qmu += __shfl_xor_sync(0xffffffffu, qmu, o);
        sl  += __shfl_xor_sync(0xffffffffu, sl, o);
    }
    if (lane == 0)
        g_C[b * LL + l] = -0.5f * qmu - 0.5f * sl - (float)DD * HALF_LOG2PI;
}

// ---------------------------------------------------------------------------
// K1: GEMM (unchanged from R9).
// ---------------------------------------------------------------------------
#define BK 16
__global__ void __launch_bounds__(256) lp_gemm(const float* __restrict__ mel,
                                               float* __restrict__ lp_out) {
    __shared__ float As [64][BK + 1];
    __shared__ float Bs1[BK][64];
    __shared__ float Bs2[BK][64];

    int b  = blockIdx.z;
    int m0 = blockIdx.x * 64;
    int n0 = blockIdx.y * 64;
    int tid = threadIdx.x;
    int tx = tid & 15, ty = tid >> 4;

    const float* melb = mel + (size_t)b * TT * DD;
    const float* Wb   = g_W + (size_t)b * KK2 * LL;

    int a_mm[4], a_kk[4], bl_kk[4], bl_nn[4];
    bool bl_ok[4];
    int a_t[4];
#pragma unroll
    for (int i = 0; i < 4; i++) {
        int lin = tid + i * 256;
        a_mm[i] = lin >> 4;  a_kk[i] = lin & 15;
        int t = m0 + a_mm[i]; if (t > TT - 1) t = TT - 1;
        a_t[i] = t;
        bl_kk[i] = lin >> 6; bl_nn[i] = lin & 63;
        bl_ok[i] = (n0 + bl_nn[i]) < LL;
    }

    float acc[4][4];
#pragma unroll
    for (int i = 0; i < 4; i++)
#pragma unroll
        for (int j = 0; j < 4; j++) acc[i][j] = 0.f;

#pragma unroll
    for (int i = 0; i < 4; i++) {
        As[a_mm[i]][a_kk[i]] = melb[(size_t)a_t[i] * DD + a_kk[i]];
        int l = n0 + bl_nn[i];
        Bs1[bl_kk[i]][bl_nn[i]] = bl_ok[i] ? Wb[(size_t)bl_kk[i] * LL + l] : 0.f;
        Bs2[bl_kk[i]][bl_nn[i]] = bl_ok[i] ? Wb[(size_t)(DD + bl_kk[i]) * LL + l] : 0.f;
    }
    __syncthreads();

    float ra[4], rb1[4], rb2[4];
    for (int it = 0; it < DD / BK; it++) {
        if (it < DD / BK - 1) {
            int k0 = (it + 1) * BK;
#pragma unroll
            for (int i = 0; i < 4; i++) {
                ra[i] = melb[(size_t)a_t[i] * DD + k0 + a_kk[i]];
                int l = n0 + bl_nn[i];
                rb1[i] = bl_ok[i] ? Wb[(size_t)(k0 + bl_kk[i]) * LL + l] : 0.f;
                rb2[i] = bl_ok[i] ? Wb[(size_t)(DD + k0 + bl_kk[i]) * LL + l] : 0.f;
            }
        }
#pragma unroll
        for (int kk = 0; kk < BK; kk++) {
            float a0 = As[ty * 4 + 0][kk];
            float a1 = As[ty * 4 + 1][kk];
            float a2 = As[ty * 4 + 2][kk];
            float a3 = As[ty * 4 + 3][kk];
            float q0 = a0 * a0, q1 = a1 * a1, q2 = a2 * a2, q3 = a3 * a3;
            float4 b1 = *(const float4*)&Bs1[kk][tx * 4];
            float4 b2 = *(const float4*)&Bs2[kk][tx * 4];
            acc[0][0] += q0 * b1.x; acc[0][1] += q0 * b1.y; acc[0][2] += q0 * b1.z; acc[0][3] += q0 * b1.w;
            acc[1][0] += q1 * b1.x; acc[1][1] += q1 * b1.y; acc[1][2] += q1 * b1.z; acc[1][3] += q1 * b1.w;
            acc[2][0] += q2 * b1.x; acc[2][1] += q2 * b1.y; acc[2][2] += q2 * b1.z; acc[2][3] += q2 * b1.w;
            acc[3][0] += q3 * b1.x; acc[3][1] += q3 * b1.y; acc[3][2] += q3 * b1.z; acc[3][3] += q3 * b1.w;
            acc[0][0] += a0 * b2.x; acc[0][1] += a0 * b2.y; acc[0][2] += a0 * b2.z; acc[0][3] += a0 * b2.w;
            acc[1][0] += a1 * b2.x; acc[1][1] += a1 * b2.y; acc[1][2] += a1 * b2.z; acc[1][3] += a1 * b2.w;
            acc[2][0] += a2 * b2.x; acc[2][1] += a2 * b2.y; acc[2][2] += a2 * b2.z; acc[2][3] += a2 * b2.w;
            acc[3][0] += a3 * b2.x; acc[3][1] += a3 * b2.y; acc[3][2] += a3 * b2.z; acc[3][3] += a3 * b2.w;
        }
        __syncthreads();
        if (it < DD / BK - 1) {
#pragma unroll
            for (int i = 0; i < 4; i++) {
                As[a_mm[i]][a_kk[i]]    = ra[i];
                Bs1[bl_kk[i]][bl_nn[i]] = rb1[i];
                Bs2[bl_kk[i]][bl_nn[i]] = rb2[i];
            }
            __syncthreads();
        }
    }

#pragma unroll
    for (int i = 0; i < 4; i++) {
        int t = m0 + ty * 4 + i;
        if (t >= TT) continue;
#pragma unroll
        for (int j = 0; j < 4; j++) {
            int l = n0 + tx * 4 + j;
            if (l < LL)
                lp_out[((size_t)b * TT + t) * LL + l] = acc[i][j] + g_C[b * LL + l];
        }
    }
}

// ---------------------------------------------------------------------------
// K2: 2-warp chunk-pipelined scan. Warp A: l = 3*lane (l in [0,96));
// Warp B: l = 96+2*lane. K=16-step chunks, warp B one chunk behind.
// Boundary alpha[95, tau] in smem buf[(tau>>4)%3][tau&15] (triple-buffered
// rows; write-after-read distance = 2 barriers, verified). One named barrier
// per chunk. lp double-buffered in registers with STATIC parity.
// ---------------------------------------------------------------------------
__device__ __forceinline__ float ex2f_(float x) {
    float r; asm("ex2.approx.ftz.f32 %0, %1;" : "=f"(r) : "f"(x)); return r;
}
__device__ __forceinline__ float lg2f_(float x) {
    float r; asm("lg2.approx.ftz.f32 %0, %1;" : "=f"(r) : "f"(x)); return r;
}
__device__ __forceinline__ float lse2_(float a, float p, float lpv) {
    float m = fmaxf(a, p);
    float d = fminf(a, p) - m;             // <= 0
    float s = lg2f_(1.f + ex2f_(d));
    return fmaf(lpv, LOG2E_F, m) + s;
}

#define SCAN_BAR() asm volatile("bar.sync 1, 64;" ::: "memory")

// Warp A chunk: NST steps from t=16*C+1; prefetch PREFROWS rows of chunk C+1
// into LVN; trailing barrier.
#define WA_CHUNK(LV, LVN, C, NST, PREFROWS)                                    \
    {                                                                          \
        int tb = 16 * (C) + 1;                                                 \
        _Pragma("unroll")                                                      \
        for (int i = 0; i < (NST); i++) {                                      \
            float top   = __shfl_up_sync(0xffffffffu, a2, 1);                  \
            float prev0 = lane ? top : NEG_INF2;                               \
            float n2 = lse2_(a2, a1,    LV[i*3+2]);                            \
            float n1 = lse2_(a1, a0,    LV[i*3+1]);                            \
            float n0 = lse2_(a0, prev0, LV[i*3+0]);                            \
            a0 = n0; a1 = n1; a2 = n2;                                         \
            int t = tb + i;                                                    \
            if (lane == 31) buf[(unsigned)(t >> 4) % 3u][t & 15] = a2;         \
            abp[0] = a0 * LN2_F; abp[1] = a1 * LN2_F; abp[2] = a2 * LN2_F;     \
            abp += LL;                                                         \
            if (t == mlb && lk >= 0) {                                         \
                float av = (lk == 0) ? a0 : ((lk == 1) ? a1 : a2);             \
                atomicAdd(loss, av * lossScale);                               \
            }                                                                  \
        }                                                                      \
        if ((PREFROWS) > 0) {                                                  \
            const float* p = lpb + (size_t)(16 * ((C) + 1) + 1) * LL + lbase;  \
            _Pragma("unroll")                                                  \
            for (int i = 0; i < 16; i++) {                                     \
                const float* q = (i < (PREFROWS)) ? p : (p - LL);              \
                LVN[i*3+0] = q[0]; LVN[i*3+1] = q[1]; LVN[i*3+2] = q[2];       \
                p += LL;                                                       \
            }                                                                  \
        }                                                                      \
        SCAN_BAR();                                                            \
    }

// Warp B chunk: leading barrier, then boundary row read, NST steps, prefetch.
#define WB_CHUNK(LV, LVN, C, NST, PREFROWS)                                    \
    {                                                                          \
        SCAN_BAR();                                                            \
        float bp[16];                                                          \
        _Pragma("unroll")                                                      \
        for (int i = 0; i < 16; i++) bp[i] = buf[(unsigned)(C) % 3u][i];       \
        int tb = 16 * (C) + 1;                                                 \
        _Pragma("unroll")                                                      \
        for (int i = 0; i < (NST); i++) {                                      \
            float top   = __shfl_up_sync(0xffffffffu, a1, 1);                  \
            float prev0 = lane ? top : bp[i];                                  \
            float n1 = lse2_(a1, a0,    LV[i*2+1]);                            \
            float n0 = lse2_(a0, prev0, LV[i*2+0]);                            \
            a0 = n0; a1 = n1;                                                  \
            int t = tb + i;                                                    \
            abp[0] = a0 * LN2_F; abp[1] = a1 * LN2_F;                          \
            abp += LL;                                                         \
            if (t == mlb && lk >= 0) {                                         \
                float av = (lk == 0) ? a0 : a1;                                \
                atomicAdd(loss, av * lossScale);                               \
            }                                                                  \
        }                                                                      \
        if ((PREFROWS) > 0) {                                                  \
            const float* p = lpb + (size_t)(16 * ((C) + 1) + 1) * LL + lbase;  \
            _Pragma("unroll")                                                  \
            for (int i = 0; i < 16; i++) {                                     \
                const float* q = (i < (PREFROWS)) ? p : (p - LL);              \
                LVN[i*2+0] = q[0]; LVN[i*2+1] = q[1];                          \
                p += LL;                                                       \
            }                                                                  \
        }                                                                      \
    }

__global__ void __launch_bounds__(64) scan_kernel(const float* __restrict__ lp,
                                                  float* __restrict__ alphas,
                                                  const int* __restrict__ ml,
                                                  const int* __restrict__ cl,
                                                  float* __restrict__ loss) {
    __shared__ float buf[3][16];

    int b = blockIdx.x;
    const float* lpb = lp + (size_t)b * TT * LL;
    float* ab = alphas + (size_t)b * TT * LL;
    int mlb = ml[b] - 1;
    int clb = cl[b] - 1;
    int w = threadIdx.x >> 5, lane = threadIdx.x & 31;
    const float lossScale = -(LN2_F / (float)BB);

    if (threadIdx.x == 0) buf[0][0] = NEG_INF2;   // alpha[95, tau=0]
    __syncthreads();

    if (w == 0) {
        // ---------------- Warp A: l in [0,96), 3 per lane ----------------
        const int lbase = lane * 3;
        int lk = (clb < 96 && clb / 3 == lane) ? (clb % 3) : -1;

        float a0 = NEG_INF2, a1 = NEG_INF2, a2 = NEG_INF2;
        if (lane == 0) a0 = lpb[0] * LOG2E_F;
        ab[lbase + 0] = a0 * LN2_F;
        ab[lbase + 1] = a1 * LN2_F;
        ab[lbase + 2] = a2 * LN2_F;

        float lvA[48], lvB[48];
        {
            const float* p = lpb + LL + lbase;       // rows 1..16
#pragma unroll
            for (int i = 0; i < 16; i++) {
                lvA[i*3+0] = p[0]; lvA[i*3+1] = p[1]; lvA[i*3+2] = p[2];
                p += LL;
            }
        }
        float* abp = ab + LL + lbase;

        for (int cc = 0; cc < 24; cc++) {
            int c0 = cc * 2;
            WA_CHUNK(lvA, lvB, c0,     16, 16)
            WA_CHUNK(lvB, lvA, c0 + 1, 16, 16)
        }
        WA_CHUNK(lvA, lvB, 48, 16, 15)    // prefetch last chunk (15 rows)
        WA_CHUNK(lvB, lvA, 49, 15, 0)     // t = 785..799
    } else {
        // ---------------- Warp B: l in [96,160), 2 per lane ----------------
        const int lbase = 96 + lane * 2;
        int lk = (clb >= 96 && (clb - 96) / 2 == lane) ? ((clb - 96) % 2) : -1;

        float a0 = NEG_INF2, a1 = NEG_INF2;   // l >= 96, never l==0
        ab[lbase + 0] = a0 * LN2_F;
        ab[lbase + 1] = a1 * LN2_F;

        float lvA[32], lvB[32];
        {
            const float* p = lpb + LL + lbase;       // rows 1..16
#pragma unroll
            for (int i = 0; i < 16; i++) {
                lvA[i*2+0] = p[0]; lvA[i*2+1] = p[1];
                p += LL;
            }
        }
        float* abp = ab + LL + lbase;

        for (int cc = 0; cc < 24; cc++) {
            int c0 = cc * 2;
            WB_CHUNK(lvA, lvB, c0,     16, 16)
            WB_CHUNK(lvB, lvA, c0 + 1, 16, 16)
        }
        WB_CHUNK(lvA, lvB, 48, 16, 15)
        WB_CHUNK(lvB, lvA, 49, 15, 0)
    }
}

// ---------------------------------------------------------------------------
extern "C" void kernel_launch(void* const* d_in, const int* in_sizes, int n_in,
                              void* d_out, int out_size) {
    const float* mel      = (const float*)d_in[0];
    const float* mu_sigma = (const float*)d_in[1];
    const int*   ml       = (const int*)d_in[2];
    const int*   cl       = (const int*)d_in[3];

    float* out    = (float*)d_out;
    float* lp     = out;                              // [B,T,L]
    float* loss   = out + (size_t)BB * TT * LL;       // [1]
    float* alphas = loss + 1;                         // [B,T,L]

    param_kernel<<<(BB * LL * 32 + 127) / 128, 128>>>(mu_sigma, loss);

    dim3 g((TT + 63) / 64, (LL + 63) / 64, BB);       // 13 x 3 x 16
    lp_gemm<<<g, 256>>>(mel, lp);

    scan_kernel<<<BB, 64>>>(lp, alphas, ml, cl, loss);
}